// round 14
// baseline (speedup 1.0000x reference)
#include <cuda_runtime.h>
#include <cuda_fp16.h>

#define Bn 4
#define Cn 32
#define Hn 512
#define Wn 512
#define HWn (Hn * Wn)
#define PSTRIP 64

// NHWC fp16 scratch copy of x: [B][H][W][C] = 64 MB
__device__ __half g_xt[(size_t)Bn * HWn * Cn];

// ---------------------------------------------------------------------------
// Pass 1 (per batch b): NCHW fp32 -> NHWC fp16. Block = 128w x 32c tile.
// Tile layout [c][w], stride 132: conflict-free in BOTH smem phases. [R9 proven]
// ---------------------------------------------------------------------------
__global__ __launch_bounds__(256) void transpose_kernel(
    const float* __restrict__ x, int b)
{
    __shared__ float tile[32 * 132];
    const int w0 = blockIdx.x * 128;
    const int h  = blockIdx.y;
    const int tid = threadIdx.x;

    const float* xb = x + (size_t)b * Cn * HWn + h * Wn + w0;
#pragma unroll
    for (int iter = 0; iter < 4; ++iter) {
        const int c  = iter * 8 + (tid >> 5);
        const int wq = tid & 31;
        const float4 v = __ldg((const float4*)(xb + (size_t)c * HWn + wq * 4));
        *(float4*)(tile + c * 132 + wq * 4) = v;
    }
    __syncthreads();

    const int pix  = tid & 127;
    const int half = tid >> 7;
    float v[16];
#pragma unroll
    for (int k = 0; k < 16; ++k)
        v[k] = tile[(half * 16 + k) * 132 + pix];

    __half2 hh[8];
#pragma unroll
    for (int j = 0; j < 8; ++j)
        hh[j] = __floats2half2_rn(v[2 * j], v[2 * j + 1]);
    uint4 u0, u1;
    u0.x = *(const unsigned int*)&hh[0];
    u0.y = *(const unsigned int*)&hh[1];
    u0.z = *(const unsigned int*)&hh[2];
    u0.w = *(const unsigned int*)&hh[3];
    u1.x = *(const unsigned int*)&hh[4];
    u1.y = *(const unsigned int*)&hh[5];
    u1.z = *(const unsigned int*)&hh[6];
    u1.w = *(const unsigned int*)&hh[7];
    char* p = (char*)(g_xt + (((size_t)b * Hn + h) * Wn + w0 + pix) * Cn) + half * 32;
    *(uint4*)p        = u0;
    *(uint4*)(p + 16) = u1;
}

// ---------------------------------------------------------------------------
// Pass 2 (per batch b): params once (smem), fp16 NHWC gathers (4 lanes x 16B
// per pixel), smem transpose, coalesced residual-add + NCHW store. [R9 proven]
// ---------------------------------------------------------------------------
__global__ __launch_bounds__(256) void warp_gather_kernel(
    const float* __restrict__ flow,
    const float* __restrict__ residual,
    float* __restrict__ out, int b)
{
    __shared__ float s_wt[4][PSTRIP];
    __shared__ int   s_of[4][PSTRIP];
    __shared__ float sres[PSTRIP * 33];

    const int w0  = blockIdx.x * PSTRIP;
    const int h   = blockIdx.y;
    const int tid = threadIdx.x;

    // ---- phase 0: 64 threads compute per-pixel sampling params ----
    if (tid < PSTRIP) {
        const int w = w0 + tid;
        const int pix = h * Wn + w;
        const float* fb = flow + (size_t)b * 2 * HWn;
        const float fx = __ldg(fb + pix);
        const float fy = __ldg(fb + HWn + pix);

        float gx = (w + 0.5f) * (2.0f / Wn) - 1.0f + fx;
        float gy = (h + 0.5f) * (2.0f / Hn) - 1.0f + fy;

        // circular wrap on x: mod(gx+1, 2) - 1
        float t = gx + 1.0f;
        t = t - floorf(t * 0.5f) * 2.0f;
        gx = t - 1.0f;

        const float rx = (gx + 1.0f) * (Wn * 0.5f) - 0.5f;
        const float ry = (gy + 1.0f) * (Hn * 0.5f) - 0.5f;

        const float x0f = floorf(rx);
        const float y0f = floorf(ry);
        const float dx = rx - x0f;
        const float dy = ry - y0f;

        const int ix0 = (int)x0f, iy0 = (int)y0f;
        const int ix1 = ix0 + 1,  iy1 = iy0 + 1;

        const float vx0 = (ix0 >= 0 && ix0 < Wn) ? 1.0f : 0.0f;
        const float vx1 = (ix1 >= 0 && ix1 < Wn) ? 1.0f : 0.0f;
        const float vy0 = (iy0 >= 0 && iy0 < Hn) ? 1.0f : 0.0f;
        const float vy1 = (iy1 >= 0 && iy1 < Hn) ? 1.0f : 0.0f;

        s_wt[0][tid] = (1.0f - dx) * (1.0f - dy) * vx0 * vy0;
        s_wt[1][tid] = dx * (1.0f - dy) * vx1 * vy0;
        s_wt[2][tid] = (1.0f - dx) * dy * vx0 * vy1;
        s_wt[3][tid] = dx * dy * vx1 * vy1;

        const int cx0 = min(max(ix0, 0), Wn - 1);
        const int cx1 = min(max(ix1, 0), Wn - 1);
        const int cy0 = min(max(iy0, 0), Hn - 1);
        const int cy1 = min(max(iy1, 0), Hn - 1);
        s_of[0][tid] = cy0 * Wn + cx0;
        s_of[1][tid] = cy0 * Wn + cx1;
        s_of[2][tid] = cy1 * Wn + cx0;
        s_of[3][tid] = cy1 * Wn + cx1;
    }
    __syncthreads();

    // ---- phase 1: gather. thread = (pixel i, 8-channel group q) ----
    {
        const int i = tid >> 2;
        const int q = tid & 3;
        const __half* xb = g_xt + (size_t)b * HWn * Cn + q * 8;

        float r[8];
#pragma unroll
        for (int k = 0; k < 8; ++k) r[k] = 0.0f;

#pragma unroll
        for (int cnr = 0; cnr < 4; ++cnr) {
            const float wt = s_wt[cnr][i];
            const uint4 ld = __ldg((const uint4*)(xb + (size_t)s_of[cnr][i] * Cn));
            const unsigned int uu[4] = {ld.x, ld.y, ld.z, ld.w};
#pragma unroll
            for (int j = 0; j < 4; ++j) {
                const float2 f = __half22float2(*(const __half2*)&uu[j]);
                r[j * 2 + 0] += wt * f.x;
                r[j * 2 + 1] += wt * f.y;
            }
        }

        float* s = sres + i * 33 + q * 8;
#pragma unroll
        for (int k = 0; k < 8; ++k) s[k] = r[k];
    }
    __syncthreads();

    // ---- phase 2: coalesced residual-add + NCHW store ----
    {
        const int wi = tid & 63;
        const int cg = tid >> 6;
        const size_t base = (size_t)b * Cn * HWn + h * Wn + w0 + wi;
#pragma unroll
        for (int cc = 0; cc < 32; cc += 4) {
            const int c = cc + cg;
            const size_t o = base + (size_t)c * HWn;
            out[o] = sres[wi * 33 + c] + __ldg(residual + o);
        }
    }
}

extern "C" void kernel_launch(void* const* d_in, const int* in_sizes, int n_in,
                              void* d_out, int out_size)
{
    const float* x        = (const float*)d_in[0];
    const float* flow     = (const float*)d_in[1];
    const float* residual = (const float*)d_in[2];
    float*       out      = (float*)d_out;

    dim3 gridT(Wn / 128, Hn);
    dim3 gridG(Wn / PSTRIP, Hn);

    // Fork a side stream for the transposes; gathers on the captured (default)
    // stream wait per-batch so G(b) overlaps T(b+1..). Host-side stream/event
    // creation only (no device memory). Not destroyed: capture may still
    // reference them; kernel_launch is called O(1) times.
    cudaStream_t s2;
    cudaStreamCreateWithFlags(&s2, cudaStreamNonBlocking);
    cudaEvent_t fork;
    cudaEventCreateWithFlags(&fork, cudaEventDisableTiming);
    cudaEventRecord(fork, 0);
    cudaStreamWaitEvent(s2, fork, 0);

    cudaEvent_t eT[Bn];
    for (int b = 0; b < Bn; ++b) {
        transpose_kernel<<<gridT, 256, 0, s2>>>(x, b);
        cudaEventCreateWithFlags(&eT[b], cudaEventDisableTiming);
        cudaEventRecord(eT[b], s2);
    }
    for (int b = 0; b < Bn; ++b) {
        cudaStreamWaitEvent(0, eT[b], 0);
        warp_gather_kernel<<<gridG, 256>>>(flow, residual, out, b);
    }
}

// round 15
// speedup vs baseline: 1.0776x; 1.0776x over previous
#include <cuda_runtime.h>
#include <cuda_fp16.h>

#define Bn 4
#define Cn 32
#define Hn 512
#define Wn 512
#define HWn (Hn * Wn)
#define PSTRIP 64

// NHWC fp16 scratch copy of x: [B][H][W][C] = 64 MB
__device__ __half g_xt[(size_t)Bn * HWn * Cn];

// 256-bit global store (sm_103 supports st.global.v8.b32)
__device__ __forceinline__ void stg256(void* p, uint4 a, uint4 b) {
    asm volatile("st.global.v8.b32 [%0], {%1,%2,%3,%4,%5,%6,%7,%8};"
                 :: "l"(p),
                    "r"(a.x), "r"(a.y), "r"(a.z), "r"(a.w),
                    "r"(b.x), "r"(b.y), "r"(b.z), "r"(b.w)
                 : "memory");
}

// ---------------------------------------------------------------------------
// Pass 1: NCHW fp32 -> NHWC fp16. Block = 128 w x 32 c tile at fixed (b,h).
// Tile layout [c][w], stride 132: conflict-free in BOTH smem phases.
// Store: ONE 256-bit store per thread (16 channels = 32B, 32B-aligned).
// ---------------------------------------------------------------------------
__global__ __launch_bounds__(256) void transpose_kernel(const float* __restrict__ x)
{
    __shared__ float tile[32 * 132];
    const int w0 = blockIdx.x * 128;
    const int h  = blockIdx.y;
    const int b  = blockIdx.z;
    const int tid = threadIdx.x;

    const float* xb = x + (size_t)b * Cn * HWn + h * Wn + w0;
#pragma unroll
    for (int iter = 0; iter < 4; ++iter) {
        const int c  = iter * 8 + (tid >> 5);
        const int wq = tid & 31;
        const float4 v = __ldg((const float4*)(xb + (size_t)c * HWn + wq * 4));
        *(float4*)(tile + c * 132 + wq * 4) = v;
    }
    __syncthreads();

    const int pix  = tid & 127;
    const int half = tid >> 7;
    float v[16];
#pragma unroll
    for (int k = 0; k < 16; ++k)
        v[k] = tile[(half * 16 + k) * 132 + pix];

    __half2 hh[8];
#pragma unroll
    for (int j = 0; j < 8; ++j)
        hh[j] = __floats2half2_rn(v[2 * j], v[2 * j + 1]);
    uint4 u0, u1;
    u0.x = *(const unsigned int*)&hh[0];
    u0.y = *(const unsigned int*)&hh[1];
    u0.z = *(const unsigned int*)&hh[2];
    u0.w = *(const unsigned int*)&hh[3];
    u1.x = *(const unsigned int*)&hh[4];
    u1.y = *(const unsigned int*)&hh[5];
    u1.z = *(const unsigned int*)&hh[6];
    u1.w = *(const unsigned int*)&hh[7];
    char* p = (char*)(g_xt + (((size_t)b * Hn + h) * Wn + w0 + pix) * Cn) + half * 32;
    stg256(p, u0, u1);
}

// ---------------------------------------------------------------------------
// Pass 2: per-pixel params once (smem broadcast), fp16 NHWC gathers with
// 4 lanes x 16B per pixel, smem transpose, coalesced residual-add + NCHW
// store. [byte-identical to the proven 60.0us R9 gather]
// ---------------------------------------------------------------------------
__global__ __launch_bounds__(256) void warp_gather_kernel(
    const float* __restrict__ flow,
    const float* __restrict__ residual,
    float* __restrict__ out)
{
    __shared__ float s_wt[4][PSTRIP];   // tl,tr,bl,br weights
    __shared__ int   s_of[4][PSTRIP];   // tl,tr,bl,br pixel offsets
    __shared__ float sres[PSTRIP * 33]; // [pixel][channel]

    const int w0  = blockIdx.x * PSTRIP;
    const int h   = blockIdx.y;
    const int b   = blockIdx.z;
    const int tid = threadIdx.x;

    // ---- phase 0: 64 threads compute per-pixel sampling params ----
    if (tid < PSTRIP) {
        const int w = w0 + tid;
        const int pix = h * Wn + w;
        const float* fb = flow + (size_t)b * 2 * HWn;
        const float fx = __ldg(fb + pix);
        const float fy = __ldg(fb + HWn + pix);

        float gx = (w + 0.5f) * (2.0f / Wn) - 1.0f + fx;
        float gy = (h + 0.5f) * (2.0f / Hn) - 1.0f + fy;

        // circular wrap on x: mod(gx+1, 2) - 1
        float t = gx + 1.0f;
        t = t - floorf(t * 0.5f) * 2.0f;
        gx = t - 1.0f;

        const float rx = (gx + 1.0f) * (Wn * 0.5f) - 0.5f;
        const float ry = (gy + 1.0f) * (Hn * 0.5f) - 0.5f;

        const float x0f = floorf(rx);
        const float y0f = floorf(ry);
        const float dx = rx - x0f;
        const float dy = ry - y0f;

        const int ix0 = (int)x0f, iy0 = (int)y0f;
        const int ix1 = ix0 + 1,  iy1 = iy0 + 1;

        const float vx0 = (ix0 >= 0 && ix0 < Wn) ? 1.0f : 0.0f;
        const float vx1 = (ix1 >= 0 && ix1 < Wn) ? 1.0f : 0.0f;
        const float vy0 = (iy0 >= 0 && iy0 < Hn) ? 1.0f : 0.0f;
        const float vy1 = (iy1 >= 0 && iy1 < Hn) ? 1.0f : 0.0f;

        s_wt[0][tid] = (1.0f - dx) * (1.0f - dy) * vx0 * vy0;
        s_wt[1][tid] = dx * (1.0f - dy) * vx1 * vy0;
        s_wt[2][tid] = (1.0f - dx) * dy * vx0 * vy1;
        s_wt[3][tid] = dx * dy * vx1 * vy1;

        const int cx0 = min(max(ix0, 0), Wn - 1);
        const int cx1 = min(max(ix1, 0), Wn - 1);
        const int cy0 = min(max(iy0, 0), Hn - 1);
        const int cy1 = min(max(iy1, 0), Hn - 1);
        s_of[0][tid] = cy0 * Wn + cx0;
        s_of[1][tid] = cy0 * Wn + cx1;
        s_of[2][tid] = cy1 * Wn + cx0;
        s_of[3][tid] = cy1 * Wn + cx1;
    }
    __syncthreads();

    // ---- phase 1: gather. thread = (pixel i, 8-channel group q) ----
    {
        const int i = tid >> 2;     // 0..63
        const int q = tid & 3;      // 0..3 (channels q*8 .. q*8+7)
        const __half* xb = g_xt + (size_t)b * HWn * Cn + q * 8;

        float r[8];
#pragma unroll
        for (int k = 0; k < 8; ++k) r[k] = 0.0f;

#pragma unroll
        for (int cnr = 0; cnr < 4; ++cnr) {
            const float wt = s_wt[cnr][i];
            const uint4 ld = __ldg((const uint4*)(xb + (size_t)s_of[cnr][i] * Cn));
            const unsigned int uu[4] = {ld.x, ld.y, ld.z, ld.w};
#pragma unroll
            for (int j = 0; j < 4; ++j) {
                const float2 f = __half22float2(*(const __half2*)&uu[j]);
                r[j * 2 + 0] += wt * f.x;
                r[j * 2 + 1] += wt * f.y;
            }
        }

        float* s = sres + i * 33 + q * 8;
#pragma unroll
        for (int k = 0; k < 8; ++k) s[k] = r[k];
    }
    __syncthreads();

    // ---- phase 2: coalesced residual-add + NCHW store ----
    {
        const int wi = tid & 63;    // 0..63
        const int cg = tid >> 6;    // 0..3
        const size_t base = (size_t)b * Cn * HWn + h * Wn + w0 + wi;
#pragma unroll
        for (int cc = 0; cc < 32; cc += 4) {
            const int c = cc + cg;
            const size_t o = base + (size_t)c * HWn;
            out[o] = sres[wi * 33 + c] + __ldg(residual + o);
        }
    }
}

extern "C" void kernel_launch(void* const* d_in, const int* in_sizes, int n_in,
                              void* d_out, int out_size)
{
    const float* x        = (const float*)d_in[0];
    const float* flow     = (const float*)d_in[1];
    const float* residual = (const float*)d_in[2];
    float*       out      = (float*)d_out;

    dim3 gridT(Wn / 128, Hn, Bn);
    transpose_kernel<<<gridT, 256>>>(x);
    dim3 gridG(Wn / PSTRIP, Hn, Bn);
    warp_gather_kernel<<<gridG, 256>>>(flow, residual, out);
}